// round 3
// baseline (speedup 1.0000x reference)
#include <cuda_runtime.h>
#include <cuda_bf16.h>
#include <math.h>

// Problem constants (fixed shapes)
#define NN      4096      // nodes
#define KIN     1433      // in features
#define NH      8         // heads
#define FOUT    64        // NH*DHD
#define LRELU   0.2f

// Attention tiling
#define TI      64        // i rows per block
#define TJ      64        // j tile in smem
#define RPT     2         // rows per thread
#define SPLITS  8         // j-axis splits
#define CHUNK   (NN / SPLITS)   // 512

// GEMM split-K
#define KSPL    4
#define KCH     359       // ceil(1433/4)

typedef unsigned long long u64;

// ---------------- scratch (no allocations allowed) ----------------
__device__ __align__(16) float g_buf[NN * FOUT];             // 1 MB
__device__ __align__(16) float2 Lbuf[NN * NH];               // (e^sl, e^{0.2 sl})
__device__ __align__(16) float2 Rbuf[NN * NH];               // (e^sr, e^{0.2 sr})
__device__ __align__(16) float pacc_buf[SPLITS * NN * FOUT]; // 8 MB (reused: gemm partials then attn partials)
__device__ __align__(16) float psum_buf[SPLITS * NN * NH];   // 1 MB partial denom

// f32x2 packed helpers (Blackwell; reachable only via PTX). "l" constraint = 64-bit int.
__device__ __forceinline__ u64 ffma2(u64 a, u64 b, u64 c) {
    u64 d;
    asm("fma.rn.f32x2 %0, %1, %2, %3;" : "=l"(d) : "l"(a), "l"(b), "l"(c));
    return d;
}
__device__ __forceinline__ u64 pack2(float lo, float hi) {
    u64 d;
    asm("mov.b64 %0, {%1, %2};" : "=l"(d) : "f"(lo), "f"(hi));
    return d;
}
__device__ __forceinline__ void unpack2(u64 d, float& lo, float& hi) {
    asm("mov.b64 {%0, %1}, %2;" : "=f"(lo), "=f"(hi) : "l"(d));
}

// ---------------- Kernel 1: g = vert @ W  (fp32 tiled GEMM, split-K) ----------------
// Grid (NN/32, KSPL). Block computes 32 rows x 64 cols over its K chunk, 256 thr.
// Writes partials into pacc_buf[s][n][64].
__global__ void __launch_bounds__(256) gemm_proj(const float* __restrict__ A,
                                                 const float* __restrict__ B)
{
    __shared__ float As[16][36];   // As[k][m], padded
    __shared__ float Bs[16][64];
    const int tid = threadIdx.x;
    const int m0  = blockIdx.x * 32;
    const int spl = blockIdx.y;
    const int kb  = spl * KCH;
    const int ke  = min(KIN, kb + KCH);
    const int tx  = tid & 15;      // cols tx*4..+4
    const int ty  = tid >> 4;      // rows ty*2..+2

    float acc[2][4] = {};

    for (int k0 = kb; k0 < ke; k0 += 16) {
        // A tile: 32 m x 16 k
        {
            const int k = tid & 15;
            const int r = tid >> 4;
            #pragma unroll
            for (int it = 0; it < 2; it++) {
                const int row = r + it * 16;
                float v = 0.f;
                if (k0 + k < ke) v = A[(size_t)(m0 + row) * KIN + k0 + k];
                As[k][row] = v;
            }
        }
        // B tile: 16 k x 64 n
        {
            const int c  = tid & 63;
            const int rb = tid >> 6;
            #pragma unroll
            for (int it = 0; it < 4; it++) {
                const int rr = rb + it * 4;
                float v = 0.f;
                if (k0 + rr < ke) v = B[(size_t)(k0 + rr) * 64 + c];
                Bs[rr][c] = v;
            }
        }
        __syncthreads();

        #pragma unroll
        for (int kk = 0; kk < 16; kk++) {
            const float a0 = As[kk][ty * 2 + 0];
            const float a1 = As[kk][ty * 2 + 1];
            const float4 b = *(const float4*)&Bs[kk][tx * 4];
            acc[0][0] += a0 * b.x; acc[0][1] += a0 * b.y;
            acc[0][2] += a0 * b.z; acc[0][3] += a0 * b.w;
            acc[1][0] += a1 * b.x; acc[1][1] += a1 * b.y;
            acc[1][2] += a1 * b.z; acc[1][3] += a1 * b.w;
        }
        __syncthreads();
    }

    #pragma unroll
    for (int i = 0; i < 2; i++) {
        float4 v = make_float4(acc[i][0], acc[i][1], acc[i][2], acc[i][3]);
        *(float4*)&pacc_buf[((size_t)spl * NN + m0 + ty * 2 + i) * 64 + tx * 4] = v;
    }
}

// ---------------- Kernel 2: reduce split-K + per-(node,head) factored exps ----------------
__global__ void __launch_bounds__(256) prep_scores(const float* __restrict__ a_l,
                                                   const float* __restrict__ a_r)
{
    const int t = blockIdx.x * blockDim.x + threadIdx.x;
    const int n = t >> 3;
    const int h = t & 7;

    float4 s0 = make_float4(0.f, 0.f, 0.f, 0.f);
    float4 s1 = s0;
    #pragma unroll
    for (int s = 0; s < KSPL; s++) {
        const float* p = &pacc_buf[((size_t)s * NN + n) * 64 + h * 8];
        const float4 p0 = *(const float4*)(p + 0);
        const float4 p1 = *(const float4*)(p + 4);
        s0.x += p0.x; s0.y += p0.y; s0.z += p0.z; s0.w += p0.w;
        s1.x += p1.x; s1.y += p1.y; s1.z += p1.z; s1.w += p1.w;
    }
    *(float4*)&g_buf[(size_t)n * 64 + h * 8 + 0] = s0;
    *(float4*)&g_buf[(size_t)n * 64 + h * 8 + 4] = s1;

    const float4 al0 = *(const float4*)&a_l[h * 8 + 0];
    const float4 al1 = *(const float4*)&a_l[h * 8 + 4];
    const float4 ar0 = *(const float4*)&a_r[h * 8 + 0];
    const float4 ar1 = *(const float4*)&a_r[h * 8 + 4];

    const float sl = s0.x*al0.x + s0.y*al0.y + s0.z*al0.z + s0.w*al0.w
                   + s1.x*al1.x + s1.y*al1.y + s1.z*al1.z + s1.w*al1.w;
    const float sr = s0.x*ar0.x + s0.y*ar0.y + s0.z*ar0.z + s0.w*ar0.w
                   + s1.x*ar1.x + s1.y*ar1.y + s1.z*ar1.z + s1.w*ar1.w;

    Lbuf[t] = make_float2(expf(sl), expf(LRELU * sl));
    Rbuf[t] = make_float2(expf(sr), expf(LRELU * sr));
}

// ---------------- Kernel 3: masked softmax-aggregation ----------------
// exp(lrelu(sl+sr)) == max(e^sl * e^sr, e^{.2 sl} * e^{.2 sr})  (exp monotone, lrelu = max of linears)
// Grid (SPLITS, NN/TI) = 512 blocks. 256 thr: h = tid&7, grp = tid>>3 (32 groups x 2 rows).
__global__ void __launch_bounds__(256) attn_kernel(const int* __restrict__ edge)
{
    __shared__ float  gs[TJ * 64];            // 16 KB
    __shared__ float2 rsf[TJ * 8];            // 4 KB: (e^sr, e^{.2 sr}) per (j,h)
    __shared__ float  esf[TI][TJ + 4];        // 17 KB: mask as float, natural [i][j]

    const int tid = threadIdx.x;
    const int h   = tid & 7;
    const int grp = tid >> 3;                 // 0..31
    const int split = blockIdx.x;
    const int i0  = blockIdx.y * TI;
    const int j0  = split * CHUNK;

    float Ei[RPT], Fi[RPT], ssum[RPT];
    u64 acc2[RPT][4];
    #pragma unroll
    for (int r = 0; r < RPT; r++) {
        const float2 L = Lbuf[(size_t)(i0 + grp * RPT + r) * 8 + h];
        Ei[r] = L.x; Fi[r] = L.y;
        ssum[r] = 0.f;
        #pragma unroll
        for (int d = 0; d < 4; d++) acc2[r][d] = pack2(0.f, 0.f);
    }

    const float4* g4 = (const float4*)g_buf;
    const int4*   e4 = (const int4*)edge;

    for (int jt = 0; jt < CHUNK; jt += TJ) {
        const int jb = j0 + jt;

        // g tile: TJ*16 float4 -> 4 per thread
        #pragma unroll
        for (int k = 0; k < (TJ * 16) / 256; k++) {
            const int idx = tid + k * 256;
            ((float4*)gs)[idx] = g4[(size_t)jb * 16 + idx];
        }
        // r tile: TJ*8 float2 -> 2 per thread
        #pragma unroll
        for (int k = 0; k < (TJ * 8) / 256; k++) {
            const int idx = tid + k * 256;
            rsf[idx] = Rbuf[(size_t)jb * 8 + idx];
        }
        // edge tile: TI x TJ ints = 1024 int4 -> 4 per thread; convert to float mask
        #pragma unroll
        for (int k = 0; k < (TI * TJ / 4) / 256; k++) {
            const int idx = tid + k * 256;
            const int ii  = idx >> 4;           // TJ/4 = 16 int4 per row
            const int jq  = idx & 15;
            const int4 v  = e4[(size_t)(i0 + ii) * (NN / 4) + (jb >> 2) + jq];
            float4 f;
            f.x = (v.x != 0) ? 1.f : 0.f;
            f.y = (v.y != 0) ? 1.f : 0.f;
            f.z = (v.z != 0) ? 1.f : 0.f;
            f.w = (v.w != 0) ? 1.f : 0.f;
            *(float4*)&esf[ii][jq * 4] = f;
        }
        __syncthreads();

        #pragma unroll 4
        for (int j = 0; j < TJ; j++) {
            const float2 EF = rsf[j * 8 + h];
            const ulonglong2* gp = (const ulonglong2*)&gs[j * 64 + h * 8];
            const ulonglong2 gA = gp[0];
            const ulonglong2 gB = gp[1];
            #pragma unroll
            for (int r = 0; r < RPT; r++) {
                const float mf = esf[grp * RPT + r][j];
                const float w  = fmaxf(Ei[r] * EF.x, Fi[r] * EF.y) * mf;
                ssum[r] += w;
                const u64 wd = pack2(w, w);
                acc2[r][0] = ffma2(wd, gA.x, acc2[r][0]);
                acc2[r][1] = ffma2(wd, gA.y, acc2[r][1]);
                acc2[r][2] = ffma2(wd, gB.x, acc2[r][2]);
                acc2[r][3] = ffma2(wd, gB.y, acc2[r][3]);
            }
        }
        __syncthreads();
    }

    // write partials
    #pragma unroll
    for (int r = 0; r < RPT; r++) {
        const int irow = i0 + grp * RPT + r;
        float* pa = &pacc_buf[((size_t)split * NN + irow) * 64 + h * 8];
        float a0, a1, a2, a3, a4, a5, a6, a7;
        unpack2(acc2[r][0], a0, a1);
        unpack2(acc2[r][1], a2, a3);
        unpack2(acc2[r][2], a4, a5);
        unpack2(acc2[r][3], a6, a7);
        *(float4*)(pa + 0) = make_float4(a0, a1, a2, a3);
        *(float4*)(pa + 4) = make_float4(a4, a5, a6, a7);
        psum_buf[((size_t)split * NN + irow) * 8 + h] = ssum[r];
    }
}

// ---------------- Kernel 4: combine splits, normalize, ELU ----------------
// One thread per (i, h): 8 outputs.
__global__ void __launch_bounds__(256) combine_kernel(float* __restrict__ out)
{
    const int t = blockIdx.x * blockDim.x + threadIdx.x;   // 0 .. NN*NH-1
    const int i = t >> 3;
    const int h = t & 7;

    float4 a0 = make_float4(0.f, 0.f, 0.f, 0.f);
    float4 a1 = a0;
    float den = 0.f;
    #pragma unroll
    for (int s = 0; s < SPLITS; s++) {
        const float* p = &pacc_buf[((size_t)s * NN + i) * 64 + h * 8];
        const float4 p0 = *(const float4*)(p + 0);
        const float4 p1 = *(const float4*)(p + 4);
        a0.x += p0.x; a0.y += p0.y; a0.z += p0.z; a0.w += p0.w;
        a1.x += p1.x; a1.y += p1.y; a1.z += p1.z; a1.w += p1.w;
        den += psum_buf[((size_t)s * NN + i) * 8 + h];
    }
    const float inv = 1.0f / den;
    float v[8] = {a0.x*inv, a0.y*inv, a0.z*inv, a0.w*inv,
                  a1.x*inv, a1.y*inv, a1.z*inv, a1.w*inv};
    float r[8];
    #pragma unroll
    for (int d = 0; d < 8; d++) r[d] = (v[d] >= 0.f) ? v[d] : expm1f(v[d]);
    float* po = &out[(size_t)i * 64 + h * 8];
    *(float4*)(po + 0) = make_float4(r[0], r[1], r[2], r[3]);
    *(float4*)(po + 4) = make_float4(r[4], r[5], r[6], r[7]);
}

// ---------------- launch ----------------
extern "C" void kernel_launch(void* const* d_in, const int* in_sizes, int n_in,
                              void* d_out, int out_size)
{
    const float* vert = (const float*)d_in[0];   // [4096,1433]
    const int*   edge = (const int*)  d_in[1];   // [4096,4096]
    const float* W    = (const float*)d_in[2];   // [1433,64]
    const float* a_l  = (const float*)d_in[3];   // [8,8]
    const float* a_r  = (const float*)d_in[4];   // [8,8]
    float* out = (float*)d_out;                  // [4096,64]

    gemm_proj<<<dim3(NN / 32, KSPL), 256>>>(vert, W);
    prep_scores<<<(NN * NH) / 256, 256>>>(a_l, a_r);
    attn_kernel<<<dim3(SPLITS, NN / TI), 256>>>(edge);
    combine_kernel<<<(NN * NH) / 256, 256>>>(out);
}

// round 4
// speedup vs baseline: 1.5059x; 1.5059x over previous
#include <cuda_runtime.h>
#include <cuda_bf16.h>
#include <math.h>

// Problem constants (fixed shapes)
#define NN      4096      // nodes
#define KIN     1433      // in features
#define NH      8         // heads
#define FOUT    64        // NH*DHD
#define LRELU   0.2f

// Attention tiling
#define TI      128       // i rows per block
#define TJ      64        // j tile in smem
#define RPT     4         // rows per thread (TI / 32 groups)
#define SPLITS  16        // j-axis splits
#define CHUNK   (NN / SPLITS)   // 256

// GEMM split-K
#define KSPL    4
#define KCH     359       // ceil(1433/4)

typedef unsigned long long u64;

// ---------------- scratch (no allocations allowed) ----------------
__device__ __align__(16) float g_buf[NN * FOUT];             // 1 MB
__device__ __align__(16) float2 Lbuf[NN * NH];               // (e^sl, e^{0.2 sl}) packed pair
__device__ __align__(16) float2 Rbuf[NN * NH];               // (e^sr, e^{0.2 sr}) packed pair
__device__ __align__(16) float pacc_buf[SPLITS * NN * FOUT]; // 16 MB (gemm partials then attn partials)
__device__ __align__(16) float psum_buf[SPLITS * NN * NH];   // 2 MB partial denom

// f32x2 packed helpers (Blackwell; PTX-only). "l" constraint = 64-bit int reg.
__device__ __forceinline__ u64 ffma2(u64 a, u64 b, u64 c) {
    u64 d;
    asm("fma.rn.f32x2 %0, %1, %2, %3;" : "=l"(d) : "l"(a), "l"(b), "l"(c));
    return d;
}
__device__ __forceinline__ u64 fmul2(u64 a, u64 b) {
    u64 d;
    asm("mul.rn.f32x2 %0, %1, %2;" : "=l"(d) : "l"(a), "l"(b));
    return d;
}
__device__ __forceinline__ u64 pack2(float lo, float hi) {
    u64 d;
    asm("mov.b64 %0, {%1, %2};" : "=l"(d) : "f"(lo), "f"(hi));
    return d;
}
__device__ __forceinline__ void unpack2(u64 d, float& lo, float& hi) {
    asm("mov.b64 {%0, %1}, %2;" : "=f"(lo), "=f"(hi) : "l"(d));
}

// ---------------- Kernel 1: g = vert @ W  (fp32 tiled GEMM, split-K) ----------------
__global__ void __launch_bounds__(256) gemm_proj(const float* __restrict__ A,
                                                 const float* __restrict__ B)
{
    __shared__ float As[16][36];   // As[k][m], padded
    __shared__ float Bs[16][64];
    const int tid = threadIdx.x;
    const int m0  = blockIdx.x * 32;
    const int spl = blockIdx.y;
    const int kb  = spl * KCH;
    const int ke  = min(KIN, kb + KCH);
    const int tx  = tid & 15;      // cols tx*4..+4
    const int ty  = tid >> 4;      // rows ty*2..+2

    float acc[2][4] = {};

    for (int k0 = kb; k0 < ke; k0 += 16) {
        {
            const int k = tid & 15;
            const int r = tid >> 4;
            #pragma unroll
            for (int it = 0; it < 2; it++) {
                const int row = r + it * 16;
                float v = 0.f;
                if (k0 + k < ke) v = A[(size_t)(m0 + row) * KIN + k0 + k];
                As[k][row] = v;
            }
        }
        {
            const int c  = tid & 63;
            const int rb = tid >> 6;
            #pragma unroll
            for (int it = 0; it < 4; it++) {
                const int rr = rb + it * 4;
                float v = 0.f;
                if (k0 + rr < ke) v = B[(size_t)(k0 + rr) * 64 + c];
                Bs[rr][c] = v;
            }
        }
        __syncthreads();

        #pragma unroll
        for (int kk = 0; kk < 16; kk++) {
            const float a0 = As[kk][ty * 2 + 0];
            const float a1 = As[kk][ty * 2 + 1];
            const float4 b = *(const float4*)&Bs[kk][tx * 4];
            acc[0][0] += a0 * b.x; acc[0][1] += a0 * b.y;
            acc[0][2] += a0 * b.z; acc[0][3] += a0 * b.w;
            acc[1][0] += a1 * b.x; acc[1][1] += a1 * b.y;
            acc[1][2] += a1 * b.z; acc[1][3] += a1 * b.w;
        }
        __syncthreads();
    }

    #pragma unroll
    for (int i = 0; i < 2; i++) {
        float4 v = make_float4(acc[i][0], acc[i][1], acc[i][2], acc[i][3]);
        *(float4*)&pacc_buf[((size_t)spl * NN + m0 + ty * 2 + i) * 64 + tx * 4] = v;
    }
}

// ---------------- Kernel 2: reduce split-K + per-(node,head) factored exps ----------------
__global__ void __launch_bounds__(256) prep_scores(const float* __restrict__ a_l,
                                                   const float* __restrict__ a_r)
{
    const int t = blockIdx.x * blockDim.x + threadIdx.x;
    const int n = t >> 3;
    const int h = t & 7;

    float4 s0 = make_float4(0.f, 0.f, 0.f, 0.f);
    float4 s1 = s0;
    #pragma unroll
    for (int s = 0; s < KSPL; s++) {
        const float* p = &pacc_buf[((size_t)s * NN + n) * 64 + h * 8];
        const float4 p0 = *(const float4*)(p + 0);
        const float4 p1 = *(const float4*)(p + 4);
        s0.x += p0.x; s0.y += p0.y; s0.z += p0.z; s0.w += p0.w;
        s1.x += p1.x; s1.y += p1.y; s1.z += p1.z; s1.w += p1.w;
    }
    *(float4*)&g_buf[(size_t)n * 64 + h * 8 + 0] = s0;
    *(float4*)&g_buf[(size_t)n * 64 + h * 8 + 4] = s1;

    const float4 al0 = *(const float4*)&a_l[h * 8 + 0];
    const float4 al1 = *(const float4*)&a_l[h * 8 + 4];
    const float4 ar0 = *(const float4*)&a_r[h * 8 + 0];
    const float4 ar1 = *(const float4*)&a_r[h * 8 + 4];

    const float sl = s0.x*al0.x + s0.y*al0.y + s0.z*al0.z + s0.w*al0.w
                   + s1.x*al1.x + s1.y*al1.y + s1.z*al1.z + s1.w*al1.w;
    const float sr = s0.x*ar0.x + s0.y*ar0.y + s0.z*ar0.z + s0.w*ar0.w
                   + s1.x*ar1.x + s1.y*ar1.y + s1.z*ar1.z + s1.w*ar1.w;

    Lbuf[t] = make_float2(expf(sl), expf(LRELU * sl));
    Rbuf[t] = make_float2(expf(sr), expf(LRELU * sr));
}

// ---------------- Kernel 3: masked softmax-aggregation ----------------
// exp(lrelu(sl+sr)) == max(e^sl * e^sr, e^{.2 sl} * e^{.2 sr})  (exp monotone; lrelu = max of linears)
// Grid (SPLITS, NN/TI) = (16, 32) = 512 blocks. 256 thr: h = tid&7, grp = tid>>3,
// thread owns RPT=4 consecutive rows for one head.
__global__ void __launch_bounds__(256) attn_kernel(const int* __restrict__ edge)
{
    __shared__ float gs[TJ * 64];                  // 16 KB: g tile
    __shared__ u64   rsu[TJ * 8];                  // 4 KB: packed (e^sr, e^{.2 sr}) per (j,h)
    __shared__ unsigned int esw[TI][TJ / 4 + 1];   // 8.5 KB: 4 j-masks per word, [i][j4]

    const int tid = threadIdx.x;
    const int h   = tid & 7;
    const int grp = tid >> 3;                 // 0..31
    const int split = blockIdx.x;
    const int i0  = blockIdx.y * TI;
    const int j0  = split * CHUNK;

    u64 EiFi[RPT];
    float ssum[RPT];
    u64 acc2[RPT][4];
    const u64* Lu = (const u64*)Lbuf;
    #pragma unroll
    for (int r = 0; r < RPT; r++) {
        EiFi[r] = Lu[(size_t)(i0 + grp * RPT + r) * 8 + h];
        ssum[r] = 0.f;
        #pragma unroll
        for (int d = 0; d < 4; d++) acc2[r][d] = 0ull;
    }

    const float4* g4 = (const float4*)g_buf;
    const u64*    Ru = (const u64*)Rbuf;
    const int4*   e4 = (const int4*)edge;

    for (int jt = 0; jt < CHUNK; jt += TJ) {
        const int jb = j0 + jt;

        // g tile: TJ*16 float4 -> 4 per thread
        #pragma unroll
        for (int k = 0; k < (TJ * 16) / 256; k++) {
            const int idx = tid + k * 256;
            ((float4*)gs)[idx] = g4[(size_t)jb * 16 + idx];
        }
        // r tile: TJ*8 u64 -> 2 per thread
        #pragma unroll
        for (int k = 0; k < (TJ * 8) / 256; k++) {
            const int idx = tid + k * 256;
            rsu[idx] = Ru[(size_t)jb * 8 + idx];
        }
        // edge tile: TI x TJ ints = 2048 int4 -> 8 per thread; pack 4 j-masks into one word
        #pragma unroll
        for (int k = 0; k < (TI * TJ / 4) / 256; k++) {
            const int idx = tid + k * 256;
            const int ii  = idx >> 4;            // row (TJ/4 = 16 int4 per row)
            const int jq  = idx & 15;            // which 4-j group
            const int4 v  = e4[(size_t)(i0 + ii) * (NN / 4) + (jb >> 2) + jq];
            unsigned int b = 0;
            b |= (v.x != 0) ? 0x01u : 0u;
            b |= (v.y != 0) ? 0x0100u : 0u;
            b |= (v.z != 0) ? 0x010000u : 0u;
            b |= (v.w != 0) ? 0x01000000u : 0u;
            esw[ii][jq] = b;
        }
        __syncthreads();

        for (int j4 = 0; j4 < TJ; j4 += 4) {
            unsigned int m[RPT];
            #pragma unroll
            for (int r = 0; r < RPT; r++) m[r] = esw[grp * RPT + r][j4 >> 2];

            #pragma unroll
            for (int jj = 0; jj < 4; jj++) {
                const int j = j4 + jj;
                const u64 EF = rsu[j * 8 + h];
                const ulonglong2 gA = *(const ulonglong2*)&gs[j * 64 + h * 8];
                const ulonglong2 gB = *(const ulonglong2*)&gs[j * 64 + h * 8 + 4];
                #pragma unroll
                for (int r = 0; r < RPT; r++) {
                    const u64 p = fmul2(EiFi[r], EF);     // both lrelu branches at once
                    float lo, hi; unpack2(p, lo, hi);
                    float w = fmaxf(lo, hi);              // FMNMX (alu pipe)
                    if (((m[r] >> (jj * 8)) & 0xffu) == 0u) w = 0.f;   // alu select
                    ssum[r] += w;
                    const u64 wd = pack2(w, w);
                    acc2[r][0] = ffma2(wd, gA.x, acc2[r][0]);
                    acc2[r][1] = ffma2(wd, gA.y, acc2[r][1]);
                    acc2[r][2] = ffma2(wd, gB.x, acc2[r][2]);
                    acc2[r][3] = ffma2(wd, gB.y, acc2[r][3]);
                }
            }
        }
        __syncthreads();
    }

    // write partials
    #pragma unroll
    for (int r = 0; r < RPT; r++) {
        const int irow = i0 + grp * RPT + r;
        float* pa = &pacc_buf[((size_t)split * NN + irow) * 64 + h * 8];
        float a0, a1, a2, a3, a4, a5, a6, a7;
        unpack2(acc2[r][0], a0, a1);
        unpack2(acc2[r][1], a2, a3);
        unpack2(acc2[r][2], a4, a5);
        unpack2(acc2[r][3], a6, a7);
        *(float4*)(pa + 0) = make_float4(a0, a1, a2, a3);
        *(float4*)(pa + 4) = make_float4(a4, a5, a6, a7);
        psum_buf[((size_t)split * NN + irow) * 8 + h] = ssum[r];
    }
}

// ---------------- Kernel 4: combine splits, normalize, ELU ----------------
// One thread per output element.
__global__ void __launch_bounds__(256) combine_kernel(float* __restrict__ out)
{
    const int t = blockIdx.x * blockDim.x + threadIdx.x;   // 0 .. NN*64-1
    const int i = t >> 6;
    const int c = t & 63;
    const int h = c >> 3;

    float a = 0.f, den = 0.f;
    #pragma unroll
    for (int s = 0; s < SPLITS; s++) {
        a   += pacc_buf[((size_t)s * NN + i) * 64 + c];
        den += psum_buf[((size_t)s * NN + i) * 8 + h];
    }
    const float v = a / den;
    out[t] = (v >= 0.f) ? v : expm1f(v);
}

// ---------------- launch ----------------
extern "C" void kernel_launch(void* const* d_in, const int* in_sizes, int n_in,
                              void* d_out, int out_size)
{
    const float* vert = (const float*)d_in[0];   // [4096,1433]
    const int*   edge = (const int*)  d_in[1];   // [4096,4096]
    const float* W    = (const float*)d_in[2];   // [1433,64]
    const float* a_l  = (const float*)d_in[3];   // [8,8]
    const float* a_r  = (const float*)d_in[4];   // [8,8]
    float* out = (float*)d_out;                  // [4096,64]

    gemm_proj<<<dim3(NN / 32, KSPL), 256>>>(vert, W);
    prep_scores<<<(NN * NH) / 256, 256>>>(a_l, a_r);
    attn_kernel<<<dim3(SPLITS, NN / TI), 256>>>(edge);
    combine_kernel<<<(NN * FOUT) / 256, 256>>>(out);
}

// round 5
// speedup vs baseline: 1.5470x; 1.0273x over previous
#include <cuda_runtime.h>
#include <cuda_bf16.h>
#include <math.h>

// Problem constants (fixed shapes)
#define NN      4096      // nodes
#define KIN     1433      // in features
#define NH      8         // heads
#define FOUT    64        // NH*DHD
#define LRELU   0.2f

// Attention tiling
#define TI      128       // i rows per block
#define TJ      64        // j tile in smem
#define RPT     4         // rows per thread (TI / 32 groups)
#define SPLITS  16        // j-axis splits
#define CHUNK   (NN / SPLITS)   // 256

// GEMM split-K (64x64 tiles)
#define GM      64
#define KSPL    8
#define KCH     180       // ceil(1433/8)

typedef unsigned long long u64;

// ---------------- scratch (no allocations allowed) ----------------
__device__ __align__(16) float g_buf[NN * FOUT];             // 1 MB
__device__ __align__(16) float2 Lbuf[NN * NH];               // (e^sl, e^{0.2 sl}) packed pair
__device__ __align__(16) float2 Rbuf[NN * NH];               // (e^sr, e^{0.2 sr}) packed pair
__device__ __align__(16) float pacc_buf[SPLITS * NN * FOUT]; // 16 MB (gemm partials then attn partials)
__device__ __align__(16) float psum_buf[SPLITS * NN * NH];   // 2 MB partial denom

// f32x2 packed helpers (Blackwell; PTX-only). "l" constraint = 64-bit int reg.
__device__ __forceinline__ u64 ffma2(u64 a, u64 b, u64 c) {
    u64 d;
    asm("fma.rn.f32x2 %0, %1, %2, %3;" : "=l"(d) : "l"(a), "l"(b), "l"(c));
    return d;
}
__device__ __forceinline__ u64 fmul2(u64 a, u64 b) {
    u64 d;
    asm("mul.rn.f32x2 %0, %1, %2;" : "=l"(d) : "l"(a), "l"(b));
    return d;
}
__device__ __forceinline__ u64 pack2(float lo, float hi) {
    u64 d;
    asm("mov.b64 %0, {%1, %2};" : "=l"(d) : "f"(lo), "f"(hi));
    return d;
}
__device__ __forceinline__ void unpack2(u64 d, float& lo, float& hi) {
    asm("mov.b64 {%0, %1}, %2;" : "=f"(lo), "=f"(hi) : "l"(d));
}
// replicate byte `jj` of m across all 4 bytes (PRMT, alu pipe)
__device__ __forceinline__ unsigned int byte_bcast(unsigned int m, unsigned int sel) {
    unsigned int d;
    asm("prmt.b32 %0, %1, %2, %3;" : "=r"(d) : "r"(m), "r"(0u), "r"(sel));
    return d;
}

// ---------------- Kernel 1: g = vert @ W  (fp32 f32x2 GEMM, split-K) ----------------
// Grid (NN/64, KSPL). Block: 64 rows x 64 cols, 256 thr, 4x4 per thread via ffma2.
__global__ void __launch_bounds__(256) gemm_proj(const float* __restrict__ A,
                                                 const float* __restrict__ B)
{
    __shared__ u64   Asd[16][66];   // A values pre-duplicated as (a,a); padded
    __shared__ float Bs[16][64];
    const int tid = threadIdx.x;
    const int m0  = blockIdx.x * GM;
    const int spl = blockIdx.y;
    const int kb  = spl * KCH;
    const int ke  = min(KIN, kb + KCH);
    const int tx  = tid & 15;      // col group: cols tx*4..+3
    const int ty  = tid >> 4;      // row group: rows ty*4..+3

    u64 acc[4][2] = {};

    for (int k0 = kb; k0 < ke; k0 += 16) {
        // A tile: 64 rows x 16 k; thread loads 4 consecutive k of one row
        {
            const int row = tid >> 2;
            const int ks  = (tid & 3) * 4;
            const float* ap = &A[(size_t)(m0 + row) * KIN + k0 + ks];
            #pragma unroll
            for (int i = 0; i < 4; i++) {
                const float v = (k0 + ks + i < ke) ? ap[i] : 0.f;
                Asd[ks + i][row] = pack2(v, v);
            }
        }
        // B tile: 16 k x 64 n
        {
            const int c  = tid & 63;
            const int rb = tid >> 6;
            #pragma unroll
            for (int it = 0; it < 4; it++) {
                const int rr = rb + it * 4;
                Bs[rr][c] = (k0 + rr < ke) ? B[(size_t)(k0 + rr) * 64 + c] : 0.f;
            }
        }
        __syncthreads();

        #pragma unroll
        for (int kk = 0; kk < 16; kk++) {
            const ulonglong2 a01 = *(const ulonglong2*)&Asd[kk][ty * 4 + 0];
            const ulonglong2 a23 = *(const ulonglong2*)&Asd[kk][ty * 4 + 2];
            const ulonglong2 b   = *(const ulonglong2*)&Bs[kk][tx * 4];
            acc[0][0] = ffma2(a01.x, b.x, acc[0][0]);
            acc[0][1] = ffma2(a01.x, b.y, acc[0][1]);
            acc[1][0] = ffma2(a01.y, b.x, acc[1][0]);
            acc[1][1] = ffma2(a01.y, b.y, acc[1][1]);
            acc[2][0] = ffma2(a23.x, b.x, acc[2][0]);
            acc[2][1] = ffma2(a23.x, b.y, acc[2][1]);
            acc[3][0] = ffma2(a23.y, b.x, acc[3][0]);
            acc[3][1] = ffma2(a23.y, b.y, acc[3][1]);
        }
        __syncthreads();
    }

    #pragma unroll
    for (int i = 0; i < 4; i++) {
        float x0, x1, x2, x3;
        unpack2(acc[i][0], x0, x1);
        unpack2(acc[i][1], x2, x3);
        *(float4*)&pacc_buf[((size_t)spl * NN + m0 + ty * 4 + i) * 64 + tx * 4] =
            make_float4(x0, x1, x2, x3);
    }
}

// ---------------- Kernel 2: reduce split-K + per-(node,head) factored exps ----------------
__global__ void __launch_bounds__(256) prep_scores(const float* __restrict__ a_l,
                                                   const float* __restrict__ a_r)
{
    const int t = blockIdx.x * blockDim.x + threadIdx.x;
    const int n = t >> 3;
    const int h = t & 7;

    float4 s0 = make_float4(0.f, 0.f, 0.f, 0.f);
    float4 s1 = s0;
    #pragma unroll
    for (int s = 0; s < KSPL; s++) {
        const float* p = &pacc_buf[((size_t)s * NN + n) * 64 + h * 8];
        const float4 p0 = *(const float4*)(p + 0);
        const float4 p1 = *(const float4*)(p + 4);
        s0.x += p0.x; s0.y += p0.y; s0.z += p0.z; s0.w += p0.w;
        s1.x += p1.x; s1.y += p1.y; s1.z += p1.z; s1.w += p1.w;
    }
    *(float4*)&g_buf[(size_t)n * 64 + h * 8 + 0] = s0;
    *(float4*)&g_buf[(size_t)n * 64 + h * 8 + 4] = s1;

    const float4 al0 = *(const float4*)&a_l[h * 8 + 0];
    const float4 al1 = *(const float4*)&a_l[h * 8 + 4];
    const float4 ar0 = *(const float4*)&a_r[h * 8 + 0];
    const float4 ar1 = *(const float4*)&a_r[h * 8 + 4];

    const float sl = s0.x*al0.x + s0.y*al0.y + s0.z*al0.z + s0.w*al0.w
                   + s1.x*al1.x + s1.y*al1.y + s1.z*al1.z + s1.w*al1.w;
    const float sr = s0.x*ar0.x + s0.y*ar0.y + s0.z*ar0.z + s0.w*ar0.w
                   + s1.x*ar1.x + s1.y*ar1.y + s1.z*ar1.z + s1.w*ar1.w;

    Lbuf[t] = make_float2(expf(sl), expf(LRELU * sl));
    Rbuf[t] = make_float2(expf(sr), expf(LRELU * sr));
}

// ---------------- Kernel 3: masked softmax-aggregation ----------------
// exp(lrelu(sl+sr)) == max(e^sl * e^sr, e^{.2 sl} * e^{.2 sr})  (exp monotone; lrelu = max of linears)
// Mask: 0xFF/0x00 bytes; applied via PRMT byte-replicate + bitwise AND on the weight.
__global__ void __launch_bounds__(256) attn_kernel(const int* __restrict__ edge)
{
    __shared__ float gs[TJ * 64];                  // 16 KB: g tile
    __shared__ u64   rsu[TJ * 8];                  // 4 KB: packed (e^sr, e^{.2 sr}) per (j,h)
    __shared__ unsigned int esw[TI][TJ / 4 + 1];   // 8.5 KB: 4 mask bytes (0xFF/0x00) per word

    const int tid = threadIdx.x;
    const int h   = tid & 7;
    const int grp = tid >> 3;                 // 0..31
    const int split = blockIdx.x;
    const int i0  = blockIdx.y * TI;
    const int j0  = split * CHUNK;

    u64 EiFi[RPT];
    float ssum[RPT];
    u64 acc2[RPT][4];
    const u64* Lu = (const u64*)Lbuf;
    #pragma unroll
    for (int r = 0; r < RPT; r++) {
        EiFi[r] = Lu[(size_t)(i0 + grp * RPT + r) * 8 + h];
        ssum[r] = 0.f;
        #pragma unroll
        for (int d = 0; d < 4; d++) acc2[r][d] = 0ull;
    }

    const float4* g4 = (const float4*)g_buf;
    const u64*    Ru = (const u64*)Rbuf;
    const int4*   e4 = (const int4*)edge;

    for (int jt = 0; jt < CHUNK; jt += TJ) {
        const int jb = j0 + jt;

        // g tile: TJ*16 float4 -> 4 per thread
        #pragma unroll
        for (int k = 0; k < (TJ * 16) / 256; k++) {
            const int idx = tid + k * 256;
            ((float4*)gs)[idx] = g4[(size_t)jb * 16 + idx];
        }
        // r tile: TJ*8 u64 -> 2 per thread
        #pragma unroll
        for (int k = 0; k < (TJ * 8) / 256; k++) {
            const int idx = tid + k * 256;
            rsu[idx] = Ru[(size_t)jb * 8 + idx];
        }
        // edge tile: TI x TJ ints = 2048 int4 -> 8 per thread; 0xFF byte per edge
        #pragma unroll
        for (int k = 0; k < (TI * TJ / 4) / 256; k++) {
            const int idx = tid + k * 256;
            const int ii  = idx >> 4;            // row (TJ/4 = 16 int4 per row)
            const int jq  = idx & 15;            // which 4-j group
            const int4 v  = e4[(size_t)(i0 + ii) * (NN / 4) + (jb >> 2) + jq];
            unsigned int b = 0;
            b |= (v.x != 0) ? 0x000000FFu : 0u;
            b |= (v.y != 0) ? 0x0000FF00u : 0u;
            b |= (v.z != 0) ? 0x00FF0000u : 0u;
            b |= (v.w != 0) ? 0xFF000000u : 0u;
            esw[ii][jq] = b;
        }
        __syncthreads();

        for (int j4 = 0; j4 < TJ; j4 += 4) {
            unsigned int m[RPT];
            #pragma unroll
            for (int r = 0; r < RPT; r++) m[r] = esw[grp * RPT + r][j4 >> 2];

            #pragma unroll
            for (int jj = 0; jj < 4; jj++) {
                const int j = j4 + jj;
                const u64 EF = rsu[j * 8 + h];
                const ulonglong2 gA = *(const ulonglong2*)&gs[j * 64 + h * 8];
                const ulonglong2 gB = *(const ulonglong2*)&gs[j * 64 + h * 8 + 4];
                const unsigned int sel = jj * 0x1111u;   // compile-time per unrolled jj
                #pragma unroll
                for (int r = 0; r < RPT; r++) {
                    const u64 p = fmul2(EiFi[r], EF);     // both lrelu branches at once
                    float lo, hi; unpack2(p, lo, hi);
                    float w = fmaxf(lo, hi);              // FMNMX (alu)
                    const unsigned int msk = byte_bcast(m[r], sel);         // PRMT (alu)
                    w = __uint_as_float(__float_as_uint(w) & msk);          // LOP3 (alu)
                    ssum[r] += w;
                    const u64 wd = pack2(w, w);
                    acc2[r][0] = ffma2(wd, gA.x, acc2[r][0]);
                    acc2[r][1] = ffma2(wd, gA.y, acc2[r][1]);
                    acc2[r][2] = ffma2(wd, gB.x, acc2[r][2]);
                    acc2[r][3] = ffma2(wd, gB.y, acc2[r][3]);
                }
            }
        }
        __syncthreads();
    }

    // write partials
    #pragma unroll
    for (int r = 0; r < RPT; r++) {
        const int irow = i0 + grp * RPT + r;
        float* pa = &pacc_buf[((size_t)split * NN + irow) * 64 + h * 8];
        float a0, a1, a2, a3, a4, a5, a6, a7;
        unpack2(acc2[r][0], a0, a1);
        unpack2(acc2[r][1], a2, a3);
        unpack2(acc2[r][2], a4, a5);
        unpack2(acc2[r][3], a6, a7);
        *(float4*)(pa + 0) = make_float4(a0, a1, a2, a3);
        *(float4*)(pa + 4) = make_float4(a4, a5, a6, a7);
        psum_buf[((size_t)split * NN + irow) * 8 + h] = ssum[r];
    }
}

// ---------------- Kernel 4: combine splits, normalize, ELU ----------------
__global__ void __launch_bounds__(256) combine_kernel(float* __restrict__ out)
{
    const int t = blockIdx.x * blockDim.x + threadIdx.x;   // 0 .. NN*64-1
    const int i = t >> 6;
    const int c = t & 63;
    const int h = c >> 3;

    float a = 0.f, den = 0.f;
    #pragma unroll
    for (int s = 0; s < SPLITS; s++) {
        a   += pacc_buf[((size_t)s * NN + i) * 64 + c];
        den += psum_buf[((size_t)s * NN + i) * 8 + h];
    }
    const float v = a / den;
    out[t] = (v >= 0.f) ? v : expm1f(v);
}

// ---------------- launch ----------------
extern "C" void kernel_launch(void* const* d_in, const int* in_sizes, int n_in,
                              void* d_out, int out_size)
{
    const float* vert = (const float*)d_in[0];   // [4096,1433]
    const int*   edge = (const int*)  d_in[1];   // [4096,4096]
    const float* W    = (const float*)d_in[2];   // [1433,64]
    const float* a_l  = (const float*)d_in[3];   // [8,8]
    const float* a_r  = (const float*)d_in[4];   // [8,8]
    float* out = (float*)d_out;                  // [4096,64]

    gemm_proj<<<dim3(NN / GM, KSPL), 256>>>(vert, W);
    prep_scores<<<(NN * NH) / 256, 256>>>(a_l, a_r);
    attn_kernel<<<dim3(SPLITS, NN / TI), 256>>>(edge);
    combine_kernel<<<(NN * FOUT) / 256, 256>>>(out);
}

// round 6
// speedup vs baseline: 1.8479x; 1.1944x over previous
#include <cuda_runtime.h>
#include <cuda_bf16.h>
#include <math.h>

// Problem constants (fixed shapes)
#define NN      4096      // nodes
#define KIN     1433      // in features
#define NH      8         // heads
#define FOUT    64        // NH*DHD
#define LRELU   0.2f

// Attention tiling (tensor-core version)
#define TIA     64        // i rows per block
#define TJ      64        // j tile in smem
#define SPLITS  16        // j-axis splits
#define CHUNK   (NN / SPLITS)   // 256

// GEMM split-K (64x64 tiles)
#define GM      64
#define KSPL    8
#define KCH     180       // ceil(1433/8)

typedef unsigned long long u64;

// ---------------- scratch (no allocations allowed) ----------------
__device__ __align__(16) float g_buf[NN * FOUT];             // 1 MB
__device__ __align__(16) float2 Lbuf[NN * NH];               // (e^sl, e^{0.2 sl}) packed pair
__device__ __align__(16) float2 Rbuf[NN * NH];               // (e^sr, e^{0.2 sr}) packed pair
__device__ __align__(16) float pacc_buf[SPLITS * NN * FOUT]; // 16 MB (gemm partials then attn partials)
__device__ __align__(16) float psum_buf[SPLITS * NN * NH];   // 2 MB partial denom

// f32x2 packed helpers (Blackwell; PTX-only). "l" constraint = 64-bit int reg.
__device__ __forceinline__ u64 ffma2(u64 a, u64 b, u64 c) {
    u64 d;
    asm("fma.rn.f32x2 %0, %1, %2, %3;" : "=l"(d) : "l"(a), "l"(b), "l"(c));
    return d;
}
__device__ __forceinline__ u64 fmul2(u64 a, u64 b) {
    u64 d;
    asm("mul.rn.f32x2 %0, %1, %2;" : "=l"(d) : "l"(a), "l"(b));
    return d;
}
__device__ __forceinline__ u64 pack2(float lo, float hi) {
    u64 d;
    asm("mov.b64 %0, {%1, %2};" : "=l"(d) : "f"(lo), "f"(hi));
    return d;
}
__device__ __forceinline__ void unpack2(u64 d, float& lo, float& hi) {
    asm("mov.b64 {%0, %1}, %2;" : "=f"(lo), "=f"(hi) : "l"(d));
}
__device__ __forceinline__ unsigned int tf32_rna(float f) {
    unsigned int r;
    asm("cvt.rna.tf32.f32 %0, %1;" : "=r"(r) : "f"(f));
    return r;
}
// w = max(Ei*Ej, Fi*Fj) * mf  — exp-free lrelu+mask weight
__device__ __forceinline__ float wmax(u64 eifi, u64 ef, float mf) {
    const u64 p = fmul2(eifi, ef);
    float lo, hi; unpack2(p, lo, hi);
    return fmaxf(lo, hi) * mf;
}
// tf32 mma: D += A(16x8) * B(8x8), A fed as raw fp32 bits (HW truncation)
__device__ __forceinline__ void mma_tf32(float* d, float a0, float a1, float a2, float a3,
                                         unsigned int b0, unsigned int b1) {
    asm volatile(
        "mma.sync.aligned.m16n8k8.row.col.f32.tf32.tf32.f32 "
        "{%0,%1,%2,%3}, {%4,%5,%6,%7}, {%8,%9}, {%0,%1,%2,%3};"
        : "+f"(d[0]), "+f"(d[1]), "+f"(d[2]), "+f"(d[3])
        : "r"(__float_as_uint(a0)), "r"(__float_as_uint(a1)),
          "r"(__float_as_uint(a2)), "r"(__float_as_uint(a3)),
          "r"(b0), "r"(b1));
}

// ---------------- Kernel 1: g = vert @ W  (fp32 f32x2 GEMM, split-K) ----------------
__global__ void __launch_bounds__(256) gemm_proj(const float* __restrict__ A,
                                                 const float* __restrict__ B)
{
    __shared__ u64   Asd[16][66];   // A values pre-duplicated as (a,a); padded
    __shared__ float Bs[16][64];
    const int tid = threadIdx.x;
    const int m0  = blockIdx.x * GM;
    const int spl = blockIdx.y;
    const int kb  = spl * KCH;
    const int ke  = min(KIN, kb + KCH);
    const int tx  = tid & 15;
    const int ty  = tid >> 4;

    u64 acc[4][2] = {};

    for (int k0 = kb; k0 < ke; k0 += 16) {
        {
            const int row = tid >> 2;
            const int ks  = (tid & 3) * 4;
            const float* ap = &A[(size_t)(m0 + row) * KIN + k0 + ks];
            #pragma unroll
            for (int i = 0; i < 4; i++) {
                const float v = (k0 + ks + i < ke) ? ap[i] : 0.f;
                Asd[ks + i][row] = pack2(v, v);
            }
        }
        {
            const int c  = tid & 63;
            const int rb = tid >> 6;
            #pragma unroll
            for (int it = 0; it < 4; it++) {
                const int rr = rb + it * 4;
                Bs[rr][c] = (k0 + rr < ke) ? B[(size_t)(k0 + rr) * 64 + c] : 0.f;
            }
        }
        __syncthreads();

        #pragma unroll
        for (int kk = 0; kk < 16; kk++) {
            const ulonglong2 a01 = *(const ulonglong2*)&Asd[kk][ty * 4 + 0];
            const ulonglong2 a23 = *(const ulonglong2*)&Asd[kk][ty * 4 + 2];
            const ulonglong2 b   = *(const ulonglong2*)&Bs[kk][tx * 4];
            acc[0][0] = ffma2(a01.x, b.x, acc[0][0]);
            acc[0][1] = ffma2(a01.x, b.y, acc[0][1]);
            acc[1][0] = ffma2(a01.y, b.x, acc[1][0]);
            acc[1][1] = ffma2(a01.y, b.y, acc[1][1]);
            acc[2][0] = ffma2(a23.x, b.x, acc[2][0]);
            acc[2][1] = ffma2(a23.x, b.y, acc[2][1]);
            acc[3][0] = ffma2(a23.y, b.x, acc[3][0]);
            acc[3][1] = ffma2(a23.y, b.y, acc[3][1]);
        }
        __syncthreads();
    }

    #pragma unroll
    for (int i = 0; i < 4; i++) {
        float x0, x1, x2, x3;
        unpack2(acc[i][0], x0, x1);
        unpack2(acc[i][1], x2, x3);
        *(float4*)&pacc_buf[((size_t)spl * NN + m0 + ty * 4 + i) * 64 + tx * 4] =
            make_float4(x0, x1, x2, x3);
    }
}

// ---------------- Kernel 2: reduce split-K + per-(node,head) factored exps ----------------
__global__ void __launch_bounds__(256) prep_scores(const float* __restrict__ a_l,
                                                   const float* __restrict__ a_r)
{
    const int t = blockIdx.x * blockDim.x + threadIdx.x;
    const int n = t >> 3;
    const int h = t & 7;

    float4 s0 = make_float4(0.f, 0.f, 0.f, 0.f);
    float4 s1 = s0;
    #pragma unroll
    for (int s = 0; s < KSPL; s++) {
        const float* p = &pacc_buf[((size_t)s * NN + n) * 64 + h * 8];
        const float4 p0 = *(const float4*)(p + 0);
        const float4 p1 = *(const float4*)(p + 4);
        s0.x += p0.x; s0.y += p0.y; s0.z += p0.z; s0.w += p0.w;
        s1.x += p1.x; s1.y += p1.y; s1.z += p1.z; s1.w += p1.w;
    }
    *(float4*)&g_buf[(size_t)n * 64 + h * 8 + 0] = s0;
    *(float4*)&g_buf[(size_t)n * 64 + h * 8 + 4] = s1;

    const float4 al0 = *(const float4*)&a_l[h * 8 + 0];
    const float4 al1 = *(const float4*)&a_l[h * 8 + 4];
    const float4 ar0 = *(const float4*)&a_r[h * 8 + 0];
    const float4 ar1 = *(const float4*)&a_r[h * 8 + 4];

    const float sl = s0.x*al0.x + s0.y*al0.y + s0.z*al0.z + s0.w*al0.w
                   + s1.x*al1.x + s1.y*al1.y + s1.z*al1.z + s1.w*al1.w;
    const float sr = s0.x*ar0.x + s0.y*ar0.y + s0.z*ar0.z + s0.w*ar0.w
                   + s1.x*ar1.x + s1.y*ar1.y + s1.z*ar1.z + s1.w*ar1.w;

    Lbuf[t] = make_float2(expf(sl), expf(LRELU * sl));
    Rbuf[t] = make_float2(expf(sr), expf(LRELU * sr));
}

// ---------------- Kernel 3: masked softmax-aggregation via tf32 mma ----------------
// exp(lrelu(sl+sr)) == max(e^sl*e^sr, e^{.2sl}*e^{.2sr}); weights built in mma A-fragment
// layout; O += P@G and ssum += P@1 on tensor cores; truncation bias cancels in the ratio.
// Block: 256 thr = 8 warps. Warp w: rows (w&3)*16..+15 of the 64-row strip, heads (w>>2)*4..+3.
__global__ void __launch_bounds__(256) attn_kernel(const int* __restrict__ edge)
{
    __shared__ u64   gp[8][64][5];      // (tf32 G[j4], tf32 G[j4+4]) pairs; [jb8][hd][j4] pad 5
    __shared__ u64   rsu[TJ * 8];       // (e^sr, e^{.2 sr}) per (j,h)
    __shared__ float msk[TIA][68];      // mask as float, stride 68 (conflict-free)

    const int tid  = threadIdx.x;
    const int lane = tid & 31;
    const int wrp  = tid >> 5;
    const int gid  = lane >> 2;     // groupID 0..7 (fragment row)
    const int tig  = lane & 3;      // thread-in-group (fragment col/k)
    const int rw   = (wrp & 3) * 16;
    const int hb   = (wrp >> 2) * 4;
    const int split = blockIdx.x;
    const int i0   = blockIdx.y * TIA;
    const int j0   = split * CHUNK;

    const u64* Lu = (const u64*)Lbuf;
    const u64* Ru = (const u64*)Rbuf;

    // Ei cache: 2 fragment rows x 4 heads (rows fixed for whole kernel)
    u64 EiF[4][2];
    #pragma unroll
    for (int hh = 0; hh < 4; hh++) {
        EiF[hh][0] = Lu[(size_t)(i0 + rw + gid) * 8 + hb + hh];
        EiF[hh][1] = Lu[(size_t)(i0 + rw + gid + 8) * 8 + hb + hh];
    }

    float accG[4][4] = {};   // O fragments per head
    float accS[4][4] = {};   // ssum fragments per head
    const unsigned int ONE_TF32 = 0x3F800000u;

    const int4* e4 = (const int4*)edge;

    for (int jt = 0; jt < CHUNK; jt += TJ) {
        const int jb = j0 + jt;
        __syncthreads();

        // stage G pairs (rna tf32): 8 jb8 x 64 hd x 4 j4 = 2048 u64
        #pragma unroll
        for (int k = 0; k < 8; k++) {
            const int idx = tid + k * 256;
            const int hd  = idx & 63;
            const int j4  = (idx >> 6) & 3;
            const int j8  = idx >> 8;
            const int jr  = jb + j8 * 8 + j4;
            const unsigned int lo = tf32_rna(g_buf[(size_t)jr * 64 + hd]);
            const unsigned int hi = tf32_rna(g_buf[(size_t)(jr + 4) * 64 + hd]);
            gp[j8][hd][j4] = ((u64)hi << 32) | lo;
        }
        // stage EF: 512 u64
        #pragma unroll
        for (int k = 0; k < 2; k++) {
            const int idx = tid + k * 256;
            rsu[idx] = Ru[(size_t)(jb + (idx >> 3)) * 8 + (idx & 7)];
        }
        // stage mask floats: TIA x TJ ints = 1024 int4
        #pragma unroll
        for (int k = 0; k < 4; k++) {
            const int idx = tid + k * 256;
            const int ii  = idx >> 4;
            const int jq  = idx & 15;
            const int4 v  = e4[(size_t)(i0 + ii) * (NN / 4) + (jb >> 2) + jq];
            float4 f;
            f.x = (v.x != 0) ? 1.f : 0.f;
            f.y = (v.y != 0) ? 1.f : 0.f;
            f.z = (v.z != 0) ? 1.f : 0.f;
            f.w = (v.w != 0) ? 1.f : 0.f;
            *(float4*)&msk[ii][jq * 4] = f;
        }
        __syncthreads();

        #pragma unroll 2
        for (int j8 = 0; j8 < 8; j8++) {
            const float mf0 = msk[rw + gid][j8 * 8 + tig];
            const float mf1 = msk[rw + gid + 8][j8 * 8 + tig];
            const float mf2 = msk[rw + gid][j8 * 8 + tig + 4];
            const float mf3 = msk[rw + gid + 8][j8 * 8 + tig + 4];
            #pragma unroll
            for (int hh = 0; hh < 4; hh++) {
                const int h = hb + hh;
                const u64 EF0 = rsu[(j8 * 8 + tig) * 8 + h];
                const u64 EF1 = rsu[(j8 * 8 + tig + 4) * 8 + h];
                const float a0 = wmax(EiF[hh][0], EF0, mf0);
                const float a1 = wmax(EiF[hh][1], EF0, mf1);
                const float a2 = wmax(EiF[hh][0], EF1, mf2);
                const float a3 = wmax(EiF[hh][1], EF1, mf3);
                const uint2 b = *(const uint2*)&gp[j8][h * 8 + gid][tig];
                mma_tf32(accG[hh], a0, a1, a2, a3, b.x, b.y);
                mma_tf32(accS[hh], a0, a1, a2, a3, ONE_TF32, ONE_TF32);
            }
        }
    }

    // epilogue: write partials
    #pragma unroll
    for (int hh = 0; hh < 4; hh++) {
        const int h = hb + hh;
        const int ir0 = i0 + rw + gid;
        const int ir1 = ir0 + 8;
        float* p0 = &pacc_buf[((size_t)split * NN + ir0) * 64 + h * 8 + tig * 2];
        float* p1 = &pacc_buf[((size_t)split * NN + ir1) * 64 + h * 8 + tig * 2];
        *(float2*)p0 = make_float2(accG[hh][0], accG[hh][1]);
        *(float2*)p1 = make_float2(accG[hh][2], accG[hh][3]);
        if (tig == 0) {
            psum_buf[((size_t)split * NN + ir0) * 8 + h] = accS[hh][0];
            psum_buf[((size_t)split * NN + ir1) * 8 + h] = accS[hh][2];
        }
    }
}

// ---------------- Kernel 4: combine splits, normalize, ELU ----------------
__global__ void __launch_bounds__(256) combine_kernel(float* __restrict__ out)
{
    const int t = blockIdx.x * blockDim.x + threadIdx.x;   // 0 .. NN*64-1
    const int i = t >> 6;
    const int c = t & 63;
    const int h = c >> 3;

    float a = 0.f, den = 0.f;
    #pragma unroll
    for (int s = 0; s < SPLITS; s++) {
        a   += pacc_buf[((size_t)s * NN + i) * 64 + c];
        den += psum_buf[((size_t)s * NN + i) * 8 + h];
    }
    const float v = a / den;
    out[t] = (v >= 0.f) ? v : expm1f(v);
}

// ---------------- launch ----------------
extern "C" void kernel_launch(void* const* d_in, const int* in_sizes, int n_in,
                              void* d_out, int out_size)
{
    const float* vert = (const float*)d_in[0];   // [4096,1433]
    const int*   edge = (const int*)  d_in[1];   // [4096,4096]
    const float* W    = (const float*)d_in[2];   // [1433,64]
    const float* a_l  = (const float*)d_in[3];   // [8,8]
    const float* a_r  = (const float*)d_in[4];   // [8,8]
    float* out = (float*)d_out;                  // [4096,64]

    gemm_proj<<<dim3(NN / GM, KSPL), 256>>>(vert, W);
    prep_scores<<<(NN * NH) / 256, 256>>>(a_l, a_r);
    attn_kernel<<<dim3(SPLITS, NN / TIA), 256>>>(edge);
    combine_kernel<<<(NN * FOUT) / 256, 256>>>(out);
}

// round 8
// speedup vs baseline: 1.9828x; 1.0730x over previous
#include <cuda_runtime.h>
#include <cuda_bf16.h>
#include <math.h>

// Problem constants (fixed shapes)
#define NN      4096      // nodes
#define KIN     1433      // in features
#define NH      8         // heads
#define FOUT    64        // NH*DHD
#define LRELU   0.2f

// Attention tiling (tensor-core version)
#define TIA     64        // i rows per block
#define TJ      64        // j tile in smem
#define SPLITS  16        // j-axis splits
#define CHUNK   (NN / SPLITS)   // 256

// GEMM split-K (128x64 tiles, 128 threads, 8x8 per thread)
#define GM      128
#define KSPL    16
#define KCH     90        // ceil(1433/16)

typedef unsigned long long u64;

// ---------------- scratch (no allocations allowed) ----------------
__device__ __align__(16) float g_buf[NN * FOUT];             // 1 MB
__device__ __align__(16) float2 Lbuf[NN * NH];               // (e^sl, e^{0.2 sl}) packed pair
__device__ __align__(16) float2 Rbuf[NN * NH];               // (e^sr, e^{0.2 sr}) packed pair
__device__ __align__(16) float pacc_buf[SPLITS * NN * FOUT]; // 16 MB (gemm partials then attn partials)
__device__ __align__(16) float psum_buf[SPLITS * NN * NH];   // 2 MB partial denom

// f32x2 packed helpers (Blackwell; PTX-only). "l" constraint = 64-bit int reg.
__device__ __forceinline__ u64 ffma2(u64 a, u64 b, u64 c) {
    u64 d;
    asm("fma.rn.f32x2 %0, %1, %2, %3;" : "=l"(d) : "l"(a), "l"(b), "l"(c));
    return d;
}
__device__ __forceinline__ u64 fmul2(u64 a, u64 b) {
    u64 d;
    asm("mul.rn.f32x2 %0, %1, %2;" : "=l"(d) : "l"(a), "l"(b));
    return d;
}
__device__ __forceinline__ u64 pack2(float lo, float hi) {
    u64 d;
    asm("mov.b64 %0, {%1, %2};" : "=l"(d) : "f"(lo), "f"(hi));
    return d;
}
__device__ __forceinline__ void unpack2(u64 d, float& lo, float& hi) {
    asm("mov.b64 {%0, %1}, %2;" : "=f"(lo), "=f"(hi) : "l"(d));
}
__device__ __forceinline__ unsigned int tf32_rna(float f) {
    unsigned int r;
    asm("cvt.rna.tf32.f32 %0, %1;" : "=r"(r) : "f"(f));
    return r;
}
// w = (max of both lrelu branches) bit-masked by mu (0xFFFFFFFF or 0)
__device__ __forceinline__ float wmax(u64 eifi, u64 ef, unsigned int mu) {
    const u64 p = fmul2(eifi, ef);
    float lo, hi; unpack2(p, lo, hi);
    const float mx = fmaxf(lo, hi);                       // FMNMX (alu)
    return __uint_as_float(__float_as_uint(mx) & mu);     // LOP3 (alu)
}
// tf32 mma: D += A(16x8) * B(8x8), A fed as raw fp32 bits (HW truncation)
__device__ __forceinline__ void mma_tf32(float* d, float a0, float a1, float a2, float a3,
                                         unsigned int b0, unsigned int b1) {
    asm volatile(
        "mma.sync.aligned.m16n8k8.row.col.f32.tf32.tf32.f32 "
        "{%0,%1,%2,%3}, {%4,%5,%6,%7}, {%8,%9}, {%0,%1,%2,%3};"
        : "+f"(d[0]), "+f"(d[1]), "+f"(d[2]), "+f"(d[3])
        : "r"(__float_as_uint(a0)), "r"(__float_as_uint(a1)),
          "r"(__float_as_uint(a2)), "r"(__float_as_uint(a3)),
          "r"(b0), "r"(b1));
}

// ---------------- Kernel 1: g = vert @ W  (f32x2 GEMM, split-K, 8x8/thread) ----------------
// Grid (NN/128, KSPL). 128 threads: tx = tid&7 (8 cols), ty = tid>>3 (8 rows).
__global__ void __launch_bounds__(128) gemm_proj(const float* __restrict__ A,
                                                 const float* __restrict__ B)
{
    __shared__ u64   Asd[16][132];  // (a,a) dup pairs; EVEN stride -> 16B-aligned rows
    __shared__ float Bs[16][68];
    const int tid = threadIdx.x;
    const int m0  = blockIdx.x * GM;
    const int spl = blockIdx.y;
    const int kb  = spl * KCH;
    const int ke  = min(KIN, kb + KCH);
    const int tx  = tid & 7;       // cols tx*8..+7
    const int ty  = tid >> 3;      // rows ty*8..+7

    u64 acc[8][4] = {};

    for (int k0 = kb; k0 < ke; k0 += 16) {
        // A tile: 128 rows x 16 k, coalesced (lanes sweep k within a row)
        {
            const int kk  = tid & 15;
            const int rb  = tid >> 4;          // 0..7
            const bool ok = (k0 + kk < ke);
            #pragma unroll
            for (int p = 0; p < 16; p++) {
                const int row = rb + p * 8;
                const float v = ok ? A[(size_t)(m0 + row) * KIN + k0 + kk] : 0.f;
                Asd[kk][row] = pack2(v, v);
            }
        }
        // B tile: 16 k x 64 n via float4
        {
            #pragma unroll
            for (int p = 0; p < 2; p++) {
                const int i4 = tid + p * 128;
                const int rr = i4 >> 4;
                const int c4 = i4 & 15;
                float4 v = make_float4(0.f, 0.f, 0.f, 0.f);
                if (k0 + rr < ke) v = *(const float4*)&B[(size_t)(k0 + rr) * 64 + c4 * 4];
                *(float4*)&Bs[rr][c4 * 4] = v;
            }
        }
        __syncthreads();

        #pragma unroll
        for (int kk = 0; kk < 16; kk++) {
            ulonglong2 a01 = *(const ulonglong2*)&Asd[kk][ty * 8 + 0];
            ulonglong2 a23 = *(const ulonglong2*)&Asd[kk][ty * 8 + 2];
            ulonglong2 a45 = *(const ulonglong2*)&Asd[kk][ty * 8 + 4];
            ulonglong2 a67 = *(const ulonglong2*)&Asd[kk][ty * 8 + 6];
            ulonglong2 b01 = *(const ulonglong2*)&Bs[kk][tx * 8 + 0];
            ulonglong2 b23 = *(const ulonglong2*)&Bs[kk][tx * 8 + 4];
            u64 ar[8] = {a01.x, a01.y, a23.x, a23.y, a45.x, a45.y, a67.x, a67.y};
            #pragma unroll
            for (int r = 0; r < 8; r++) {
                acc[r][0] = ffma2(ar[r], b01.x, acc[r][0]);
                acc[r][1] = ffma2(ar[r], b01.y, acc[r][1]);
                acc[r][2] = ffma2(ar[r], b23.x, acc[r][2]);
                acc[r][3] = ffma2(ar[r], b23.y, acc[r][3]);
            }
        }
        __syncthreads();
    }

    #pragma unroll
    for (int r = 0; r < 8; r++) {
        float x0, x1, x2, x3, x4, x5, x6, x7;
        unpack2(acc[r][0], x0, x1);
        unpack2(acc[r][1], x2, x3);
        unpack2(acc[r][2], x4, x5);
        unpack2(acc[r][3], x6, x7);
        float* p = &pacc_buf[((size_t)spl * NN + m0 + ty * 8 + r) * 64 + tx * 8];
        *(float4*)(p + 0) = make_float4(x0, x1, x2, x3);
        *(float4*)(p + 4) = make_float4(x4, x5, x6, x7);
    }
}

// ---------------- Kernel 2: reduce split-K + per-(node,head) factored exps ----------------
__global__ void __launch_bounds__(256) prep_scores(const float* __restrict__ a_l,
                                                   const float* __restrict__ a_r)
{
    const int t = blockIdx.x * blockDim.x + threadIdx.x;
    const int n = t >> 3;
    const int h = t & 7;

    float4 s0 = make_float4(0.f, 0.f, 0.f, 0.f);
    float4 s1 = s0;
    #pragma unroll
    for (int s = 0; s < KSPL; s++) {
        const float* p = &pacc_buf[((size_t)s * NN + n) * 64 + h * 8];
        const float4 p0 = *(const float4*)(p + 0);
        const float4 p1 = *(const float4*)(p + 4);
        s0.x += p0.x; s0.y += p0.y; s0.z += p0.z; s0.w += p0.w;
        s1.x += p1.x; s1.y += p1.y; s1.z += p1.z; s1.w += p1.w;
    }
    *(float4*)&g_buf[(size_t)n * 64 + h * 8 + 0] = s0;
    *(float4*)&g_buf[(size_t)n * 64 + h * 8 + 4] = s1;

    const float4 al0 = *(const float4*)&a_l[h * 8 + 0];
    const float4 al1 = *(const float4*)&a_l[h * 8 + 4];
    const float4 ar0 = *(const float4*)&a_r[h * 8 + 0];
    const float4 ar1 = *(const float4*)&a_r[h * 8 + 4];

    const float sl = s0.x*al0.x + s0.y*al0.y + s0.z*al0.z + s0.w*al0.w
                   + s1.x*al1.x + s1.y*al1.y + s1.z*al1.z + s1.w*al1.w;
    const float sr = s0.x*ar0.x + s0.y*ar0.y + s0.z*ar0.z + s0.w*ar0.w
                   + s1.x*ar1.x + s1.y*ar1.y + s1.z*ar1.z + s1.w*ar1.w;

    Lbuf[t] = make_float2(expf(sl), expf(LRELU * sl));
    Rbuf[t] = make_float2(expf(sr), expf(LRELU * sr));
}

// ---------------- Kernel 3: masked softmax-aggregation via tf32 mma ----------------
// Weights built in mma A-fragment layout; O += P@G on tensor cores; denominator via
// FADD row-sums (+ 4-lane shfl reduce in epilogue). Mask = bitwise AND (alu pipe).
__global__ void __launch_bounds__(256, 3) attn_kernel(const int* __restrict__ edge)
{
    __shared__ u64 gp[8][64][4];           // 16 KB: (tf32 G[j4], tf32 G[j4+4]) pairs
    __shared__ u64 rsu[TJ * 8];            // 4 KB: (e^sr, e^{.2 sr}) per (j,h)
    __shared__ unsigned int msk[TIA][68];  // 17 KB: 0xFFFFFFFF/0 per (i,j)

    const int tid  = threadIdx.x;
    const int lane = tid & 31;
    const int wrp  = tid >> 5;
    const int gid  = lane >> 2;     // fragment row 0..7
    const int tig  = lane & 3;      // fragment col/k group
    const int rw   = (wrp & 3) * 16;
    const int hb   = (wrp >> 2) * 4;
    const int split = blockIdx.x;
    const int i0   = blockIdx.y * TIA;
    const int j0   = split * CHUNK;

    const u64* Lu = (const u64*)Lbuf;
    const u64* Ru = (const u64*)Rbuf;

    u64 EiF[4][2];
    #pragma unroll
    for (int hh = 0; hh < 4; hh++) {
        EiF[hh][0] = Lu[(size_t)(i0 + rw + gid) * 8 + hb + hh];
        EiF[hh][1] = Lu[(size_t)(i0 + rw + gid + 8) * 8 + hb + hh];
    }

    float accG[4][4] = {};   // O fragments per head
    float sL0[4] = {}, sL1[4] = {};   // denominator partial sums (rows gid, gid+8)

    const int4* e4 = (const int4*)edge;

    for (int jt = 0; jt < CHUNK; jt += TJ) {
        const int jb = j0 + jt;
        __syncthreads();

        // stage G pairs (rna tf32): each g row converted exactly once
        #pragma unroll
        for (int k = 0; k < 8; k++) {
            const int idx = tid + k * 256;
            const int hd  = (idx >> 2) & 63;
            const int j4  = idx & 3;
            const int j8  = idx >> 8;
            const int jr  = jb + j8 * 8 + j4;
            const unsigned int lo = tf32_rna(g_buf[(size_t)jr * 64 + hd]);
            const unsigned int hi = tf32_rna(g_buf[(size_t)(jr + 4) * 64 + hd]);
            gp[j8][hd][j4] = ((u64)hi << 32) | lo;
        }
        // stage EF
        #pragma unroll
        for (int k = 0; k < 2; k++) {
            const int idx = tid + k * 256;
            rsu[idx] = Ru[(size_t)(jb + (idx >> 3)) * 8 + (idx & 7)];
        }
        // stage mask words (0xFFFFFFFF / 0)
        #pragma unroll
        for (int k = 0; k < 4; k++) {
            const int idx = tid + k * 256;
            const int ii  = idx >> 4;
            const int jq  = idx & 15;
            const int4 v  = e4[(size_t)(i0 + ii) * (NN / 4) + (jb >> 2) + jq];
            uint4 f;
            f.x = (v.x != 0) ? 0xFFFFFFFFu : 0u;
            f.y = (v.y != 0) ? 0xFFFFFFFFu : 0u;
            f.z = (v.z != 0) ? 0xFFFFFFFFu : 0u;
            f.w = (v.w != 0) ? 0xFFFFFFFFu : 0u;
            *(uint4*)&msk[ii][jq * 4] = f;
        }
        __syncthreads();

        #pragma unroll 2
        for (int j8 = 0; j8 < 8; j8++) {
            const unsigned int mu0 = msk[rw + gid][j8 * 8 + tig];
            const unsigned int mu1 = msk[rw + gid + 8][j8 * 8 + tig];
            const unsigned int mu2 = msk[rw + gid][j8 * 8 + tig + 4];
            const unsigned int mu3 = msk[rw + gid + 8][j8 * 8 + tig + 4];
            // EF for head pairs: hb..hb+3 are adjacent u64s -> LDS128 pairs
            const ulonglong2 e0a = *(const ulonglong2*)&rsu[(j8 * 8 + tig) * 8 + hb];
            const ulonglong2 e0b = *(const ulonglong2*)&rsu[(j8 * 8 + tig) * 8 + hb + 2];
            const ulonglong2 e1a = *(const ulonglong2*)&rsu[(j8 * 8 + tig + 4) * 8 + hb];
            const ulonglong2 e1b = *(const ulonglong2*)&rsu[(j8 * 8 + tig + 4) * 8 + hb + 2];
            const u64 EF0[4] = {e0a.x, e0a.y, e0b.x, e0b.y};
            const u64 EF1[4] = {e1a.x, e1a.y, e1b.x, e1b.y};
            #pragma unroll
            for (int hh = 0; hh < 4; hh++) {
                const int h = hb + hh;
                const float a0 = wmax(EiF[hh][0], EF0[hh], mu0);
                const float a1 = wmax(EiF[hh][1], EF0[hh], mu1);
                const float a2 = wmax(EiF[hh][0], EF1[hh], mu2);
                const float a3 = wmax(EiF[hh][1], EF1[hh], mu3);
                sL0[hh] += a0 + a2;
                sL1[hh] += a1 + a3;
                const uint2 b = *(const uint2*)&gp[j8][h * 8 + gid][tig];
                mma_tf32(accG[hh], a0, a1, a2, a3, b.x, b.y);
            }
        }
    }

    // epilogue: reduce denominators over the 4-lane tig group, write partials
    #pragma unroll
    for (int hh = 0; hh < 4; hh++) {
        float s0 = sL0[hh], s1 = sL1[hh];
        s0 += __shfl_xor_sync(0xFFFFFFFFu, s0, 1);
        s0 += __shfl_xor_sync(0xFFFFFFFFu, s0, 2);
        s1 += __shfl_xor_sync(0xFFFFFFFFu, s1, 1);
        s1 += __shfl_xor_sync(0xFFFFFFFFu, s1, 2);

        const int h = hb + hh;
        const int ir0 = i0 + rw + gid;
        const int ir1 = ir0 + 8;
        float* p0 = &pacc_buf[((size_t)split * NN + ir0) * 64 + h * 8 + tig * 2];
        float* p1 = &pacc_buf[((size_t)split * NN + ir1) * 64 + h * 8 + tig * 2];
        *(float2*)p0 = make_float2(accG[hh][0], accG[hh][1]);
        *(float2*)p1 = make_float2(accG[hh][2], accG[hh][3]);
        if (tig == 0) {
            psum_buf[((size_t)split * NN + ir0) * 8 + h] = s0;
            psum_buf[((size_t)split * NN + ir1) * 8 + h] = s1;
        }
    }
}

// ---------------- Kernel 4: combine splits, normalize, ELU ----------------
__global__ void __launch_bounds__(256) combine_kernel(float* __restrict__ out)
{
    const int t = blockIdx.x * blockDim.x + threadIdx.x;   // 0 .. NN*64-1
    const int i = t >> 6;
    const int c = t & 63;
    const int h = c >> 3;

    float a = 0.f, den = 0.f;
    #pragma unroll
    for (int s = 0; s < SPLITS; s++) {
        a   += pacc_buf[((size_t)s * NN + i) * 64 + c];
        den += psum_buf[((size_t)s * NN + i) * 8 + h];
    }
    const float v = a / den;
    out[t] = (v >= 0.f) ? v : expm1f(v);
}

// ---------------- launch ----------------
extern "C" void kernel_launch(void* const* d_in, const int* in_sizes, int n_in,
                              void* d_out, int out_size)
{
    const float* vert = (const float*)d_in[0];   // [4096,1433]
    const int*   edge = (const int*)  d_in[1];   // [4096,4096]
    const float* W    = (const float*)d_in[2];   // [1433,64]
    const float* a_l  = (const float*)d_in[3];   // [8,8]
    const float* a_r  = (const float*)d_in[4];   // [8,8]
    float* out = (float*)d_out;                  // [4096,64]

    gemm_proj<<<dim3(NN / GM, KSPL), 128>>>(vert, W);
    prep_scores<<<(NN * NH) / 256, 256>>>(a_l, a_r);
    attn_kernel<<<dim3(SPLITS, NN / TIA), 256>>>(edge);
    combine_kernel<<<(NN * FOUT) / 256, 256>>>(out);
}